// round 5
// baseline (speedup 1.0000x reference)
#include <cuda_runtime.h>
#include <cstdint>
#include <math.h>

#define BATCH   65536
#define NUMC    512
#define DIM     256
#define BM      64
#define BN      128
#define NT      (NUMC/BN)      // 4
#define THREADS 256
#define NBLOCKS (BATCH/BM)     // 1024
#define ALPHA   0.05f
#define FINF    3.402823466e38f

// smem byte offsets
#define SA      0              // A fp8 64x256                       (16384)
#define SB0     16384          // B buf 0 fp8 128x256                (32768)
#define SB1     49152          // B buf 1                            (32768)
#define SCSQ    81920          // 512 f                              (2048)
#define SMV     83968          // 64x4 f                             (1024)
#define SMI     84992          // 64x4 i                             (1024)
#define SIDX    86016          // 64 i                               (256)
#define SDST    86272          // 64 f                               (256)
#define SMEM_TOTAL 86528

__device__ float g_csq[NUMC];
__device__ __align__(16) uint32_t g_cenF8[NUMC * DIM / 4];   // e4m3 x4, [n][k]
__device__ float g_partials[NBLOCKS];

// ---------------- helpers ----------------
__device__ __forceinline__ uint32_t smem_u32(const void* p) {
    uint32_t a;
    asm("{ .reg .u64 t; cvta.to.shared.u64 t, %1; cvt.u32.u64 %0, t; }"
        : "=r"(a) : "l"(p));
    return a;
}
__device__ __forceinline__ uint32_t f8pack(float4 v) {
    uint16_t lo, hi;
    asm("cvt.rn.satfinite.e4m3x2.f32 %0, %1, %2;" : "=h"(lo) : "f"(v.y), "f"(v.x));
    asm("cvt.rn.satfinite.e4m3x2.f32 %0, %1, %2;" : "=h"(hi) : "f"(v.w), "f"(v.z));
    uint32_t r; asm("mov.b32 %0, {%1,%2};" : "=r"(r) : "h"(lo), "h"(hi));
    return r;
}
__device__ __forceinline__ void mma8(float c[4], const uint32_t a[4],
                                     uint32_t b0, uint32_t b1) {
    asm volatile(
        "mma.sync.aligned.m16n8k32.row.col.f32.e4m3.e4m3.f32 "
        "{%0,%1,%2,%3}, {%4,%5,%6,%7}, {%8,%9}, {%0,%1,%2,%3};"
        : "+f"(c[0]), "+f"(c[1]), "+f"(c[2]), "+f"(c[3])
        : "r"(a[0]), "r"(a[1]), "r"(a[2]), "r"(a[3]), "r"(b0), "r"(b1));
}
#define LDSM4(r, a)                                                            \
    asm volatile("ldmatrix.sync.aligned.m8n8.x4.shared.b16 {%0,%1,%2,%3}, [%4];" \
        : "=r"((r)[0]), "=r"((r)[1]), "=r"((r)[2]), "=r"((r)[3]) : "r"(a))
#define CP_ASYNC16(dst, src) \
    asm volatile("cp.async.cg.shared.global [%0], [%1], 16;" :: "r"(dst), "l"(src))
#define CP_COMMIT()  asm volatile("cp.async.commit_group;" ::: "memory")
#define CP_WAIT0()   asm volatile("cp.async.wait_group 0;" ::: "memory")

// ---------------------------------------------------------------------------
// Kernel 0: center norms (exact fp32) + e4m3 copy of centers, [n][k] layout.
// One warp per center.
// ---------------------------------------------------------------------------
__global__ void prep_kernel(const float* __restrict__ cen) {
    int w    = blockIdx.x * 8 + (threadIdx.x >> 5);
    int lane = threadIdx.x & 31;
    const float4* row4 = (const float4*)(cen + (size_t)w * DIM);
    float s = 0.f;
    #pragma unroll
    for (int i = 0; i < 2; i++) {
        float4 v = row4[lane + 32 * i];
        s += v.x * v.x + v.y * v.y + v.z * v.z + v.w * v.w;
        g_cenF8[w * 64 + lane + 32 * i] = f8pack(v);
    }
    #pragma unroll
    for (int off = 16; off; off >>= 1)
        s += __shfl_xor_sync(0xffffffffu, s, off);
    if (lane == 0) g_csq[w] = s;
}

// ---------------------------------------------------------------------------
// Kernel 1: fp8 mma.sync GEMM (argmin search) + exact fp32 recompute of the
// selected distance. BM=64, BN=128, 8 warps (2M x 4N), warp tile 32x32.
// ---------------------------------------------------------------------------
extern __shared__ char smem[];

__device__ __forceinline__ void cp_tile(uint32_t dstbase, int t, int tid) {
    const char* src = (const char*)g_cenF8 + (size_t)t * BN * 256;
    #pragma unroll
    for (int s = 0; s < 8; s++) {
        int idx = tid + s * THREADS;
        int n = idx >> 4, c = idx & 15;
        uint32_t dst = dstbase + n * 256 + (uint32_t)((c ^ (n & 7)) << 4);
        CP_ASYNC16(dst, src + n * 256 + c * 16);
    }
    CP_COMMIT();
}

__global__ void __launch_bounds__(THREADS, 2)
kmeans_main(const float* __restrict__ emb, const float* __restrict__ cen) {
    const uint32_t sb = smem_u32(smem);
    const int tid   = threadIdx.x;
    const int w     = tid >> 5, lane = tid & 31;
    const int tig   = lane & 3, g = lane >> 2;
    const int warpM = w >> 2, warpN = w & 3;

    // kick off B tile 0 (overlaps A prologue)
    cp_tile(sb + SB0, 0, tid);

    // ---- A prologue: 4 threads/row, fp32 -> e4m3, swizzled smem store ----
    {
        const int row = tid >> 2, part = tid & 3;
        const float4* x4 = (const float4*)emb
                         + (size_t)(blockIdx.x * BM + row) * 64 + part * 16;
        char* dstrow = smem + SA + row * 256;
        const int key = row & 7;
        #pragma unroll
        for (int j = 0; j < 4; j++) {
            uint4 u;
            u.x = f8pack(x4[j * 4 + 0]);
            u.y = f8pack(x4[j * 4 + 1]);
            u.z = f8pack(x4[j * 4 + 2]);
            u.w = f8pack(x4[j * 4 + 3]);
            int c = part * 4 + j;
            *(uint4*)(dstrow + ((c ^ key) << 4)) = u;
        }
    }
    ((float*)(smem + SCSQ))[tid]       = g_csq[tid];
    ((float*)(smem + SCSQ))[tid + 256] = g_csq[tid + 256];

    CP_WAIT0();
    __syncthreads();

    // ---- ldmatrix base addresses (XOR-advanced by ks<<5) ----
    uint32_t AB[2];
    {
        const uint32_t r15 = lane & 15, hi = lane >> 4;
        #pragma unroll
        for (int mi = 0; mi < 2; mi++) {
            uint32_t row = warpM * 32 + mi * 16 + r15;
            AB[mi] = sb + SA + row * 256 + (((hi ^ (row & 7)) & 7) << 4);
        }
    }
    uint32_t BB[2][2];
    {
        const uint32_t cp = (lane >> 3) & 1;
        #pragma unroll
        for (int p = 0; p < 2; p++) {
            uint32_t n = warpN * 32 + p * 16 + (lane >> 4) * 8 + (lane & 7);
            uint32_t rel = n * 256 + (((cp ^ (n & 7)) & 7) << 4);
            BB[0][p] = sb + SB0 + rel;
            BB[1][p] = sb + SB1 + rel;
        }
    }

    const float* csq_s = (const float*)(smem + SCSQ);
    float rm[2][2] = {{FINF, FINF}, {FINF, FINF}};
    int   ri[2][2] = {{0, 0}, {0, 0}};

    for (int t = 0; t < NT; t++) {
        if (t + 1 < NT)
            cp_tile(sb + (((t + 1) & 1) ? SB1 : SB0), t + 1, tid);
        const int tb = t & 1;

        float c[2][4][4];
        #pragma unroll
        for (int mi = 0; mi < 2; mi++)
            #pragma unroll
            for (int nj = 0; nj < 4; nj++)
                #pragma unroll
                for (int q = 0; q < 4; q++) c[mi][nj][q] = 0.f;

        #pragma unroll
        for (int ks = 0; ks < 8; ks++) {
            const uint32_t ko = (uint32_t)ks << 5;
            uint32_t a0[4], a1[4], b0[4], b1[4];
            LDSM4(a0, AB[0] ^ ko);
            LDSM4(a1, AB[1] ^ ko);
            LDSM4(b0, BB[tb][0] ^ ko);
            LDSM4(b1, BB[tb][1] ^ ko);
            mma8(c[0][0], a0, b0[0], b0[1]);
            mma8(c[1][0], a1, b0[0], b0[1]);
            mma8(c[0][1], a0, b0[2], b0[3]);
            mma8(c[1][1], a1, b0[2], b0[3]);
            mma8(c[0][2], a0, b1[0], b1[1]);
            mma8(c[1][2], a1, b1[0], b1[1]);
            mma8(c[0][3], a0, b1[2], b1[3]);
            mma8(c[1][3], a1, b1[2], b1[3]);
        }

        // epilogue: cand = ||c||^2 - 2 x.c ; track (min, argmin)
        #pragma unroll
        for (int mi = 0; mi < 2; mi++)
            #pragma unroll
            for (int nj = 0; nj < 4; nj++) {
                int col = t * BN + warpN * 32 + ((nj >> 1) << 4) + ((nj & 1) << 3)
                        + 2 * tig;
                #pragma unroll
                for (int q = 0; q < 4; q++) {
                    int cc = col + (q & 1);
                    float v = csq_s[cc] - 2.f * c[mi][nj][q];
                    int h = q >> 1;
                    if (v < rm[mi][h]) { rm[mi][h] = v; ri[mi][h] = cc; }
                }
            }

        if (t + 1 < NT) { CP_WAIT0(); __syncthreads(); }
    }

    // ---- reduce (min, idx) across tig lanes, then across warpN via smem ----
    #pragma unroll
    for (int off = 1; off <= 2; off <<= 1) {
        #pragma unroll
        for (int mi = 0; mi < 2; mi++)
            #pragma unroll
            for (int h = 0; h < 2; h++) {
                float ov = __shfl_xor_sync(0xffffffffu, rm[mi][h], off);
                int   oi = __shfl_xor_sync(0xffffffffu, ri[mi][h], off);
                if (ov < rm[mi][h] || (ov == rm[mi][h] && oi < ri[mi][h])) {
                    rm[mi][h] = ov; ri[mi][h] = oi;
                }
            }
    }
    float* mv = (float*)(smem + SMV);
    int*   mi_ = (int*)(smem + SMI);
    if (tig == 0) {
        #pragma unroll
        for (int mi = 0; mi < 2; mi++)
            #pragma unroll
            for (int h = 0; h < 2; h++) {
                int row = warpM * 32 + mi * 16 + g + 8 * h;
                mv[row * 4 + warpN] = rm[mi][h];
                mi_[row * 4 + warpN] = ri[mi][h];
            }
    }
    __syncthreads();
    if (tid < 64) {
        float bv = mv[tid * 4]; int bi = mi_[tid * 4];
        #pragma unroll
        for (int j = 1; j < 4; j++) {
            float v = mv[tid * 4 + j]; int i = mi_[tid * 4 + j];
            if (v < bv || (v == bv && i < bi)) { bv = v; bi = i; }
        }
        ((int*)(smem + SIDX))[tid] = bi;
    }
    __syncthreads();

    // ---- exact fp32 recompute of the selected distance (4 threads/row) ----
    {
        const int row = tid >> 2, part = tid & 3;
        const int idx = ((const int*)(smem + SIDX))[row];
        const float4* x4 = (const float4*)emb
                         + (size_t)(blockIdx.x * BM + row) * 64 + part * 16;
        const float4* c4 = (const float4*)cen + (size_t)idx * 64 + part * 16;
        float s = 0.f;
        #pragma unroll
        for (int j = 0; j < 16; j++) {
            float4 a = x4[j], b = c4[j];
            float dx = a.x - b.x, dy = a.y - b.y;
            float dz = a.z - b.z, dw = a.w - b.w;
            s += dx * dx + dy * dy + dz * dz + dw * dw;
        }
        s += __shfl_xor_sync(0xffffffffu, s, 1);
        s += __shfl_xor_sync(0xffffffffu, s, 2);
        if (part == 0) ((float*)(smem + SDST))[row] = sqrtf(s);
    }
    __syncthreads();
    if (tid < 32) {
        const float* d = (const float*)(smem + SDST);
        float v = d[tid] + d[tid + 32];
        #pragma unroll
        for (int off = 16; off; off >>= 1)
            v += __shfl_xor_sync(0xffffffffu, v, off);
        if (tid == 0) g_partials[blockIdx.x] = v;
    }
}

// ---------------------------------------------------------------------------
// Kernel 2: deterministic tree reduce of 1024 block partials -> scalar.
// ---------------------------------------------------------------------------
__global__ void finalize_kernel(float* __restrict__ out) {
    __shared__ float s[512];
    int tid = threadIdx.x;
    s[tid] = g_partials[tid] + g_partials[tid + 512];
    __syncthreads();
    #pragma unroll
    for (int off = 256; off; off >>= 1) {
        if (tid < off) s[tid] += s[tid + off];
        __syncthreads();
    }
    if (tid == 0) out[0] = s[0] * (ALPHA / (float)BATCH);
}

// ---------------------------------------------------------------------------
extern "C" void kernel_launch(void* const* d_in, const int* in_sizes, int n_in,
                              void* d_out, int out_size) {
    const float* emb;
    const float* cen;
    if (in_sizes[0] == BATCH * DIM) {
        emb = (const float*)d_in[0];
        cen = (const float*)d_in[1];
    } else {
        emb = (const float*)d_in[1];
        cen = (const float*)d_in[0];
    }
    float* out = (float*)d_out;

    cudaFuncSetAttribute(kmeans_main,
                         cudaFuncAttributeMaxDynamicSharedMemorySize, SMEM_TOTAL);

    prep_kernel<<<NUMC / 8, 256>>>(cen);
    kmeans_main<<<NBLOCKS, THREADS, SMEM_TOTAL>>>(emb, cen);
    finalize_kernel<<<1, 512>>>(out);
}